// round 15
// baseline (speedup 1.0000x reference)
#include <cuda_runtime.h>
#include <cuda_bf16.h>
#include <cstdint>

// Problem constants
#define BB    16
#define NN    785
#define CC    768
#define HH    12
#define HD    64
#define MROWS (BB * NN)      // 12560
#define QKVN  (3 * CC)       // 2304
#define WXY   28
#define RELW  55
#define BROWS 896            // padded query rows for bias (7 * 128)
#define BSTR  836
#define KDIM  768
#define NCHUNK 24            // 768 / 32
#define LOG2E 1.4426950408889634f

// -------- scratch (static device arrays; no allocations allowed) ----------
__device__ float g_x32[MROWS * CC];          // x rounded to tf32
__device__ float g_wq [QKVN * CC];           // qkv_w rounded to tf32
__device__ float g_wp [CC * CC];             // proj_w rounded to tf32
__device__ float g_q  [BB * HH * NN * HD];   // [B,H,N,64], Q scaled 1/8*log2e
__device__ float g_k  [BB * HH * NN * HD];
__device__ float g_v  [BB * HH * NN * HD];
__device__ float g_ao [MROWS * CC];          // attention out (tf32-rounded)
__device__ float g_bias[HH * BROWS * BSTR];  // [h][i][j] bias*log2e (pads 0)

// ---------------------------------------------------------------------------
__device__ __forceinline__ uint32_t smem_u32(const void* p) {
    uint32_t a;
    asm("{ .reg .u64 t; cvta.to.shared.u64 t, %1; cvt.u32.u64 %0, t; }"
        : "=r"(a) : "l"(p));
    return a;
}
__device__ __forceinline__ float rna_tf32(float v) {
    uint32_t u;
    asm("cvt.rna.tf32.f32 %0, %1;" : "=r"(u) : "f"(v));
    return __uint_as_float(u);
}
__device__ __forceinline__ float ex2(float x) {
    float r;
    asm("ex2.approx.f32 %0, %1;" : "=f"(r) : "f"(x));
    return r;
}
__device__ __forceinline__ void mma_tf32(float* d, const uint32_t* a,
                                         const uint32_t* b) {
    asm volatile(
        "mma.sync.aligned.m16n8k8.row.col.f32.tf32.tf32.f32 "
        "{%0,%1,%2,%3}, {%4,%5,%6,%7}, {%8,%9}, {%0,%1,%2,%3};"
        : "+f"(d[0]), "+f"(d[1]), "+f"(d[2]), "+f"(d[3])
        : "r"(a[0]), "r"(a[1]), "r"(a[2]), "r"(a[3]), "r"(b[0]), "r"(b[1]));
}
// ldmatrix x4: 4 b16 8x8 = 2 tf32 8x8 matrices (one A m16k8 frag or two B frags)
__device__ __forceinline__ void ldsm4(uint32_t* r, uint32_t addr) {
    asm volatile(
        "ldmatrix.sync.aligned.m8n8.x4.shared.b16 {%0,%1,%2,%3}, [%4];"
        : "=r"(r[0]), "=r"(r[1]), "=r"(r[2]), "=r"(r[3]) : "r"(addr));
}

// ---------------------------------------------------------------------------
// tf32 rounding pre-pass, all three tensors in one launch.
// ---------------------------------------------------------------------------
#define N4X (MROWS * CC / 4)
#define N4Q (QKVN * CC / 4)
#define N4P (CC * CC / 4)

__global__ void __launch_bounds__(256)
round_all(const float* __restrict__ x, const float* __restrict__ wq,
          const float* __restrict__ wp)
{
    int i = blockIdx.x * 256 + threadIdx.x;
    const float* src;
    float* dst;
    if (i < N4X)                  { src = x;  dst = g_x32; }
    else if (i < N4X + N4Q)       { src = wq; dst = g_wq;  i -= N4X; }
    else if (i < N4X + N4Q + N4P) { src = wp; dst = g_wp;  i -= N4X + N4Q; }
    else return;
    float4 v = reinterpret_cast<const float4*>(src)[i];
    v.x = rna_tf32(v.x); v.y = rna_tf32(v.y);
    v.z = rna_tf32(v.z); v.w = rna_tf32(v.w);
    reinterpret_cast<float4*>(dst)[i] = v;
}

// ---------------------------------------------------------------------------
// tf32 mma.sync NT GEMM — 3-stage cp.async, one sync per chunk,
// fragments via ldmatrix.b16 (round-12 verified version, unchanged).
// ---------------------------------------------------------------------------
#define ASTRIDE   36
#define ABLK_F    (128 * ASTRIDE)
#define STAGE_F   (2 * ABLK_F)
#define GEMM_SMEM (3 * STAGE_F * 4)      // 110592 B -> 2 CTAs/SM

template <int MODE>
__global__ void __launch_bounds__(256, 2)
gemm_mma(const float* __restrict__ bias, float* __restrict__ Cout, int M)
{
    extern __shared__ float sm[];
    const uint32_t sbase = smem_u32(sm);

    const float* __restrict__ A  = (MODE == 0) ? g_x32 : g_ao;
    const float* __restrict__ Bm = (MODE == 0) ? g_wq  : g_wp;

    const int tid    = threadIdx.x;
    const int blockM = blockIdx.y * 128;
    const int blockN = blockIdx.x * 128;

    const int lrow  = tid >> 1;
    const int lhalf = tid & 1;
    const int arow  = blockM + lrow;
    const bool aok  = arow < M;
    const float* aptr = A  + (size_t)(aok ? arow : 0) * KDIM + lhalf * 16;
    const float* bptr = Bm + (size_t)(blockN + lrow) * KDIM + lhalf * 16;
    const uint32_t adst = sbase + (uint32_t)(lrow * ASTRIDE + lhalf * 16) * 4;
    const uint32_t bdst = adst + ABLK_F * 4;
    const int asz = aok ? 16 : 0;

#define LOADC(c) do {                                                          \
        uint32_t _so = ((c) % 3) * (STAGE_F * 4);                              \
        const float* _as = aptr + (c) * 32;                                    \
        const float* _bs = bptr + (c) * 32;                                    \
        _Pragma("unroll")                                                      \
        for (int _i = 0; _i < 4; ++_i)                                         \
            asm volatile("cp.async.cg.shared.global [%0], [%1], 16, %2;"       \
                :: "r"(adst + _so + _i * 16), "l"(_as + _i * 4), "r"(asz));    \
        _Pragma("unroll")                                                      \
        for (int _i = 0; _i < 4; ++_i)                                         \
            asm volatile("cp.async.cg.shared.global [%0], [%1], 16, 16;"       \
                :: "r"(bdst + _so + _i * 16), "l"(_bs + _i * 4));              \
        asm volatile("cp.async.commit_group;");                                \
    } while (0)

    const int lane  = tid & 31;
    const int wid   = tid >> 5;
    const int warpM = (wid & 3) * 32;
    const int warpN = (wid >> 2) * 64;
    const int tq    = lane >> 2;
    const int tr    = lane & 3;

    const int lj = lane >> 3;            // matrix index 0..3
    const int lr = lane & 7;             // row within matrix
    const uint32_t aoff =
        (uint32_t)((warpM + ((lj & 1) << 3) + lr) * ASTRIDE + ((lj >> 1) << 2)) * 4;
    const uint32_t boff = (uint32_t)ABLK_F * 4 +
        (uint32_t)((warpN + ((lj >> 1) << 3) + lr) * ASTRIDE + ((lj & 1) << 2)) * 4;

    float acc[2][8][4];
#pragma unroll
    for (int mt = 0; mt < 2; ++mt)
#pragma unroll
        for (int nt = 0; nt < 8; ++nt)
#pragma unroll
            for (int e = 0; e < 4; ++e) acc[mt][nt][e] = 0.f;

    LOADC(0);
    LOADC(1);

    for (int c = 0; c < NCHUNK; ++c) {
        if (c + 1 < NCHUNK) asm volatile("cp.async.wait_group 1;");
        else                asm volatile("cp.async.wait_group 0;");
        __syncthreads();
        if (c + 2 < NCHUNK) LOADC(c + 2);

        const uint32_t stg = sbase + (uint32_t)((c % 3) * STAGE_F * 4);

#pragma unroll
        for (int ks = 0; ks < 4; ++ks) {
            uint32_t af[2][4];
#pragma unroll
            for (int mt = 0; mt < 2; ++mt)
                ldsm4(af[mt], stg + aoff +
                      (uint32_t)((mt * 16 * ASTRIDE + ks * 8) * 4));
            uint32_t bf[4][4];
#pragma unroll
            for (int p = 0; p < 4; ++p)
                ldsm4(bf[p], stg + boff +
                      (uint32_t)((p * 16 * ASTRIDE + ks * 8) * 4));
#pragma unroll
            for (int p = 0; p < 4; ++p)
#pragma unroll
                for (int mt = 0; mt < 2; ++mt) {
                    mma_tf32(acc[mt][2 * p],     af[mt], &bf[p][0]);
                    mma_tf32(acc[mt][2 * p + 1], af[mt], &bf[p][2]);
                }
        }
    }
#undef LOADC

#pragma unroll
    for (int mt = 0; mt < 2; ++mt) {
#pragma unroll
        for (int half = 0; half < 2; ++half) {
            const int row = blockM + warpM + mt * 16 + tq + half * 8;
            if (row >= M) continue;
            int b = 0, n = 0;
            if (MODE == 0) { b = row / NN; n = row - b * NN; }
#pragma unroll
            for (int nt = 0; nt < 8; ++nt) {
                const int col = blockN + warpN + nt * 8 + tr * 2;
                const float vx = acc[mt][nt][half * 2 + 0];
                const float vy = acc[mt][nt][half * 2 + 1];
                if (MODE == 0) {
                    const int s   = col / CC;
                    const int rem = col - s * CC;
                    const int h   = rem >> 6;
                    const int d   = rem & 63;
                    const float scl = (s == 0) ? (0.125f * LOG2E) : 1.f;
                    float* dp = (s == 0 ? g_q : (s == 1 ? g_k : g_v)) +
                                (((size_t)b * HH + h) * NN + n) * HD + d;
                    *reinterpret_cast<float2*>(dp) = make_float2(vx * scl, vy * scl);
                } else {
                    *reinterpret_cast<float2*>(Cout + (size_t)row * CC + col) =
                        make_float2(vx + bias[col], vy + bias[col + 1]);
                }
            }
        }
    }
}

// ---------------------------------------------------------------------------
// Bias precompute, pre-scaled by log2e (rows 0..784; pad rows stay zero)
// ---------------------------------------------------------------------------
__global__ void __launch_bounds__(256)
bias_kernel(const float* __restrict__ rel_table,
            const float* __restrict__ g2l,
            const float* __restrict__ g2g)
{
    const int h = blockIdx.x;
    const int i = blockIdx.y;
    float* row = g_bias + ((size_t)h * BROWS + i) * BSTR;
    const int xi = (i - 1) / WXY, yi = (i - 1) % WXY;
    for (int j = threadIdx.x; j < NN; j += 256) {
        float v;
        if (i == 0)      v = (j == 0) ? g2g[h] : g2l[h];
        else if (j == 0) v = g2l[HH + h];
        else {
            int xj = (j - 1) / WXY, yj = (j - 1) % WXY;
            int idx = (xi - xj + (WXY - 1)) * RELW + (yi - yj + (WXY - 1));
            v = rel_table[idx * HH + h];
        }
        row[j] = v * LOG2E;
    }
}

// ---------------------------------------------------------------------------
// Flash attention on mma.sync tf32.  KT=64, 2-stage cp.async, one sync/tile,
// base-2 softmax; K+P via ldmatrix.  KV load mapping: full 64-float rows.
// ---------------------------------------------------------------------------
#define KT     64
#define NKT    13                         // ceil(785/64)
#define QP_F   (128 * 68)                 // 8704
#define KS_F   (KT * 68)                  // 4352
#define VS_F   (KT * 72)                  // 4608
#define ATTN_SMEM ((QP_F + 2 * (KS_F + VS_F)) * 4)   // 106496 B -> 2 CTA/SM

__global__ void __launch_bounds__(256, 2)
attn_mma()
{
    extern __shared__ float sm[];
    float* QP = sm;                       // Q staging, then P (per-warp rows)
    const uint32_t sbase = smem_u32(sm);

    const int bh = blockIdx.y;
    const int b  = bh / HH;
    const int h  = bh - b * HH;
    const int q0 = blockIdx.x * 128;

    const int tid  = threadIdx.x;
    const int lane = tid & 31;
    const int wid  = tid >> 5;
    const int tq   = lane >> 2;
    const int tr   = lane & 3;
    const int r0   = wid * 16;

    const float* Qg = g_q + (size_t)bh * NN * HD;
    const float* Kg = g_k + (size_t)bh * NN * HD;
    const float* Vg = g_v + (size_t)bh * NN * HD;
    const float* Bh = g_bias + (size_t)h * BROWS * BSTR;

    // ldmatrix per-lane row bases
    const int lj = lane >> 3;
    const int lr = lane & 7;
    // K (B-type): 16 rows x 8k per call, stride 68
    const uint32_t koff =
        (uint32_t)(((((lj >> 1) << 3) + lr) * 68) + ((lj & 1) << 2)) * 4;
    // P/Q (A-type): per-warp rows, stride 68
    const uint32_t poff =
        (uint32_t)(((r0 + ((lj & 1) << 3) + lr) * 68) + ((lj >> 1) << 2)) * 4;

    // ---- stage Q tile [128][64] into QP (stride 68) ----
#pragma unroll
    for (int u = 0; u < 8; ++u) {
        const int lin = tid + u * 256;
        const int row = lin >> 4;
        const int c4  = (lin & 15) * 4;
        const int gi  = q0 + row;
        float4 v = make_float4(0.f, 0.f, 0.f, 0.f);
        if (gi < NN) v = *reinterpret_cast<const float4*>(Qg + (size_t)gi * HD + c4);
        *reinterpret_cast<float4*>(QP + row * 68 + c4) = v;
    }
    __syncthreads();

    // ---- Q A-fragments to registers (loop-invariant; via ldmatrix) ----
    uint32_t qf[8][4];
#pragma unroll
    for (int ks = 0; ks < 8; ++ks)
        ldsm4(qf[ks], sbase + poff + (uint32_t)(ks * 8 * 4));
    __syncthreads();    // QP now free -> P buffer

    // ---- K/V cp.async: 64 rows x 64 floats each; 4 row-groups of 16 ----
    const int lrowKV = tid >> 4;          // 0..15
    const int lc4KV  = (tid & 15) * 4;    // 0..60 (full row coverage)

#define KV_LOAD(kt) do {                                                        \
        const int _k0 = (kt) * KT;                                              \
        const uint32_t _ks = sbase + (QP_F + ((kt) & 1) * (KS_F + VS_F)) * 4;   \
        const uint32_t _vs = _ks + KS_F * 4;                                    \
        _Pragma("unroll")                                                       \
        for (int _u = 0; _u < 4; ++_u) {                                        \
            const int _r = lrowKV + _u * 16;                                    \
            const int _j = _k0 + _r;                                            \
            const int _sz = (_j < NN) ? 16 : 0;                                 \
            asm volatile("cp.async.cg.shared.global [%0], [%1], 16, %2;"        \
                :: "r"(_ks + (_r * 68 + lc4KV) * 4),                            \
                   "l"(Kg + (size_t)_j * HD + lc4KV), "r"(_sz));                \
            asm volatile("cp.async.cg.shared.global [%0], [%1], 16, %2;"        \
                :: "r"(_vs + (_r * 72 + lc4KV) * 4),                            \
                   "l"(Vg + (size_t)_j * HD + lc4KV), "r"(_sz));                \
        }                                                                       \
        asm volatile("cp.async.commit_group;");                                 \
    } while (0)

    float oacc[8][4];
#pragma unroll
    for (int nt = 0; nt < 8; ++nt)
#pragma unroll
        for (int e = 0; e < 4; ++e) oacc[nt][e] = 0.f;
    float mrow[2] = {-1e30f, -1e30f};
    float lrow_s[2] = {0.f, 0.f};

    KV_LOAD(0);

    for (int kt = 0; kt < NKT; ++kt) {
        const int k0 = kt * KT;
        asm volatile("cp.async.wait_group 0;");   // tile kt landed
        __syncthreads();   // all warps done with tile kt-1 (buffer (kt+1)&1)
        if (kt + 1 < NKT) KV_LOAD(kt + 1);        // overlaps with compute kt

        const uint32_t ksAddr = sbase + (QP_F + (kt & 1) * (KS_F + VS_F)) * 4;
        const float*   Vs     = sm + QP_F + (kt & 1) * (KS_F + VS_F) + KS_F;

        // ---- S = Q K^T  (128 x 64), K fragments via ldmatrix ----
        float sacc[8][4];
#pragma unroll
        for (int nt = 0; nt < 8; ++nt)
#pragma unroll
            for (int e = 0; e < 4; ++e) sacc[nt][e] = 0.f;

#pragma unroll
        for (int ks = 0; ks < 8; ++ks) {
            uint32_t bk[4][4];
#pragma unroll
            for (int p = 0; p < 4; ++p)
                ldsm4(bk[p], ksAddr + koff +
                      (uint32_t)((p * 16 * 68 + ks * 8) * 4));
#pragma unroll
            for (int p = 0; p < 4; ++p) {
                mma_tf32(sacc[2 * p],     qf[ks], &bk[p][0]);
                mma_tf32(sacc[2 * p + 1], qf[ks], &bk[p][2]);
            }
        }

        // ---- bias add (already log2e-scaled) ----
#pragma unroll
        for (int nt = 0; nt < 8; ++nt) {
#pragma unroll
            for (int hh = 0; hh < 2; ++hh) {
                const int row = q0 + r0 + tq + 8 * hh;
                const int col = k0 + nt * 8 + 2 * tr;
                const float2 bb = __ldg(reinterpret_cast<const float2*>(
                    Bh + (size_t)row * BSTR + col));
                sacc[nt][2 * hh + 0] += bb.x;
                sacc[nt][2 * hh + 1] += bb.y;
            }
        }
        // ---- mask invalid keys (last tile only) ----
        if (k0 + KT > NN) {
#pragma unroll
            for (int nt = 0; nt < 8; ++nt)
#pragma unroll
                for (int e = 0; e < 4; ++e) {
                    const int col = k0 + nt * 8 + 2 * tr + (e & 1);
                    if (col >= NN) sacc[nt][e] = -1e30f;
                }
        }

        // ---- online softmax, base 2 (rows tq, tq+8; quad-local) ----
#pragma unroll
        for (int hh = 0; hh < 2; ++hh) {
            float mx = -1e30f;
#pragma unroll
            for (int nt = 0; nt < 8; ++nt)
                mx = fmaxf(mx, fmaxf(sacc[nt][2 * hh], sacc[nt][2 * hh + 1]));
            mx = fmaxf(mx, __shfl_xor_sync(0xffffffffu, mx, 1));
            mx = fmaxf(mx, __shfl_xor_sync(0xffffffffu, mx, 2));
            const float mnew = fmaxf(mrow[hh], mx);
            const float corr = ex2(mrow[hh] - mnew);
            mrow[hh] = mnew;
            float ps = 0.f;
#pragma unroll
            for (int nt = 0; nt < 8; ++nt) {
                const float e0 = ex2(sacc[nt][2 * hh] - mnew);
                const float e1 = ex2(sacc[nt][2 * hh + 1] - mnew);
                sacc[nt][2 * hh] = e0; sacc[nt][2 * hh + 1] = e1;
                ps += e0 + e1;
            }
            ps += __shfl_xor_sync(0xffffffffu, ps, 1);
            ps += __shfl_xor_sync(0xffffffffu, ps, 2);
            lrow_s[hh] = lrow_s[hh] * corr + ps;
#pragma unroll
            for (int nt = 0; nt < 8; ++nt) {
                oacc[nt][2 * hh] *= corr;
                oacc[nt][2 * hh + 1] *= corr;
            }
        }

        // ---- stage P to smem (per-warp rows; warp-local hazard only) ----
#pragma unroll
        for (int nt = 0; nt < 8; ++nt) {
            *reinterpret_cast<float2*>(QP + (r0 + tq) * 68 + nt * 8 + 2 * tr) =
                make_float2(sacc[nt][0], sacc[nt][1]);
            *reinterpret_cast<float2*>(QP + (r0 + tq + 8) * 68 + nt * 8 + 2 * tr) =
                make_float2(sacc[nt][2], sacc[nt][3]);
        }
        __syncwarp();

        // ---- O += P V  (k-dim = 64), P fragments via ldmatrix ----
#pragma unroll
        for (int ks = 0; ks < 8; ++ks) {
            uint32_t af[4];
            ldsm4(af, sbase + poff + (uint32_t)(ks * 8 * 4));
#pragma unroll
            for (int nt = 0; nt < 8; ++nt) {
                const float* bp = Vs + (ks * 8 + tr) * 72 + nt * 8 + tq;
                uint32_t bf[2] = { __float_as_uint(bp[0]),
                                   __float_as_uint(bp[4 * 72]) };
                mma_tf32(oacc[nt], af, bf);
            }
        }
        // no end-of-loop sync: next iteration's single sync covers reuse
    }
#undef KV_LOAD

    // ---- normalize + write g_ao (tf32-rounded) ----
#pragma unroll
    for (int hh = 0; hh < 2; ++hh) {
        const int i = q0 + r0 + tq + 8 * hh;
        if (i < NN) {
            const float inv = 1.f / lrow_s[hh];
#pragma unroll
            for (int nt = 0; nt < 8; ++nt) {
                float2 w = make_float2(oacc[nt][2 * hh] * inv,
                                       oacc[nt][2 * hh + 1] * inv);
                w.x = rna_tf32(w.x); w.y = rna_tf32(w.y);
                *reinterpret_cast<float2*>(
                    g_ao + ((size_t)b * NN + i) * CC + h * HD + nt * 8 + 2 * tr) = w;
            }
        }
    }
}

// ---------------------------------------------------------------------------
extern "C" void kernel_launch(void* const* d_in, const int* in_sizes, int n_in,
                              void* d_out, int out_size)
{
    const float* x         = (const float*)d_in[0];
    const float* qkv_w     = (const float*)d_in[1];
    const float* proj_w    = (const float*)d_in[2];
    const float* proj_b    = (const float*)d_in[3];
    const float* rel_table = (const float*)d_in[4];
    const float* g2l       = (const float*)d_in[5];
    const float* g2g       = (const float*)d_in[6];
    float* out = (float*)d_out;

    (void)in_sizes; (void)n_in; (void)out_size;

    cudaFuncSetAttribute(attn_mma,
                         cudaFuncAttributeMaxDynamicSharedMemorySize, ATTN_SMEM);
    cudaFuncSetAttribute(gemm_mma<0>,
                         cudaFuncAttributeMaxDynamicSharedMemorySize, GEMM_SMEM);
    cudaFuncSetAttribute(gemm_mma<1>,
                         cudaFuncAttributeMaxDynamicSharedMemorySize, GEMM_SMEM);

    // 0) tf32 rounding (single launch) + bias precompute
    {
        int n4 = N4X + N4Q + N4P;
        round_all<<<(n4 + 255) / 256, 256>>>(x, qkv_w, proj_w);
        dim3 gb(HH, NN);
        bias_kernel<<<gb, 256>>>(rel_table, g2l, g2g);
    }
    // 1) QKV GEMM (tf32 mma.sync + ldmatrix)
    {
        dim3 grid(QKVN / 128, (MROWS + 127) / 128);   // (18, 99)
        gemm_mma<0><<<grid, 256, GEMM_SMEM>>>(nullptr, nullptr, MROWS);
    }
    // 2) flash attention (tf32 mma.sync + ldmatrix, KT=64) -> g_ao
    {
        dim3 grid((NN + 127) / 128, BB * HH);         // (7, 192)
        attn_mma<<<grid, 256, ATTN_SMEM>>>();
    }
    // 3) proj GEMM (tf32 mma.sync + ldmatrix) + bias -> out
    {
        dim3 grid(CC / 128, (MROWS + 127) / 128);     // (6, 99)
        gemm_mma<1><<<grid, 256, GEMM_SMEM>>>(proj_b, out, MROWS);
    }
}

// round 16
// speedup vs baseline: 1.0134x; 1.0134x over previous
#include <cuda_runtime.h>
#include <cuda_bf16.h>
#include <cstdint>

// Problem constants
#define BB    16
#define NN    785
#define CC    768
#define HH    12
#define HD    64
#define MROWS (BB * NN)      // 12560
#define QKVN  (3 * CC)       // 2304
#define WXY   28
#define RELW  55
#define BROWS 896            // padded query rows for bias (7 * 128)
#define BSTR  836
#define KDIM  768
#define NCHUNK 24            // 768 / 32
#define LOG2E 1.4426950408889634f

// -------- scratch (static device arrays; no allocations allowed) ----------
__device__ float g_x32[MROWS * CC];          // x rounded to tf32
__device__ float g_wq [QKVN * CC];           // qkv_w rounded to tf32
__device__ float g_wp [CC * CC];             // proj_w rounded to tf32
__device__ float g_q  [BB * HH * NN * HD];   // [B,H,N,64], Q scaled 1/8*log2e
__device__ float g_k  [BB * HH * NN * HD];
__device__ float g_v  [BB * HH * NN * HD];
__device__ float g_ao [MROWS * CC];          // attention out (tf32-rounded)
__device__ float g_bias[HH * BROWS * BSTR];  // [h][i][j] bias*log2e (pads 0)

// ---------------------------------------------------------------------------
__device__ __forceinline__ uint32_t smem_u32(const void* p) {
    uint32_t a;
    asm("{ .reg .u64 t; cvta.to.shared.u64 t, %1; cvt.u32.u64 %0, t; }"
        : "=r"(a) : "l"(p));
    return a;
}
__device__ __forceinline__ float rna_tf32(float v) {
    uint32_t u;
    asm("cvt.rna.tf32.f32 %0, %1;" : "=r"(u) : "f"(v));
    return __uint_as_float(u);
}
__device__ __forceinline__ float ex2(float x) {
    float r;
    asm("ex2.approx.f32 %0, %1;" : "=f"(r) : "f"(x));
    return r;
}
__device__ __forceinline__ void mma_tf32(float* d, const uint32_t* a,
                                         const uint32_t* b) {
    asm volatile(
        "mma.sync.aligned.m16n8k8.row.col.f32.tf32.tf32.f32 "
        "{%0,%1,%2,%3}, {%4,%5,%6,%7}, {%8,%9}, {%0,%1,%2,%3};"
        : "+f"(d[0]), "+f"(d[1]), "+f"(d[2]), "+f"(d[3])
        : "r"(a[0]), "r"(a[1]), "r"(a[2]), "r"(a[3]), "r"(b[0]), "r"(b[1]));
}
// ldmatrix x4: one call = one tf32 A-fragment (m16k8) or two B-fragments (n8k8)
__device__ __forceinline__ void ldsm4(uint32_t* r, uint32_t addr) {
    asm volatile(
        "ldmatrix.sync.aligned.m8n8.x4.shared.b16 {%0,%1,%2,%3}, [%4];"
        : "=r"(r[0]), "=r"(r[1]), "=r"(r[2]), "=r"(r[3]) : "r"(addr));
}

// ---------------------------------------------------------------------------
// tf32 rounding pre-pass, all three tensors in one launch.
// ---------------------------------------------------------------------------
#define N4X (MROWS * CC / 4)
#define N4Q (QKVN * CC / 4)
#define N4P (CC * CC / 4)

__global__ void __launch_bounds__(256)
round_all(const float* __restrict__ x, const float* __restrict__ wq,
          const float* __restrict__ wp)
{
    int i = blockIdx.x * 256 + threadIdx.x;
    const float* src;
    float* dst;
    if (i < N4X)                  { src = x;  dst = g_x32; }
    else if (i < N4X + N4Q)       { src = wq; dst = g_wq;  i -= N4X; }
    else if (i < N4X + N4Q + N4P) { src = wp; dst = g_wp;  i -= N4X + N4Q; }
    else return;
    float4 v = reinterpret_cast<const float4*>(src)[i];
    v.x = rna_tf32(v.x); v.y = rna_tf32(v.y);
    v.z = rna_tf32(v.z); v.w = rna_tf32(v.w);
    reinterpret_cast<float4*>(dst)[i] = v;
}

// ---------------------------------------------------------------------------
// tf32 mma.sync NT GEMM — 3-stage cp.async, one sync per chunk,
// fragments via ldmatrix.b16 (A: 2 ldsm/ks, B: 4 ldsm/ks).
// ---------------------------------------------------------------------------
#define ASTRIDE   36
#define ABLK_F    (128 * ASTRIDE)
#define STAGE_F   (2 * ABLK_F)
#define GEMM_SMEM (3 * STAGE_F * 4)      // 110592 B -> 2 CTAs/SM

template <int MODE>
__global__ void __launch_bounds__(256, 2)
gemm_mma(const float* __restrict__ bias, float* __restrict__ Cout, int M)
{
    extern __shared__ float sm[];
    const uint32_t sbase = smem_u32(sm);

    const float* __restrict__ A  = (MODE == 0) ? g_x32 : g_ao;
    const float* __restrict__ Bm = (MODE == 0) ? g_wq  : g_wp;

    const int tid    = threadIdx.x;
    const int blockM = blockIdx.y * 128;
    const int blockN = blockIdx.x * 128;

    const int lrow  = tid >> 1;
    const int lhalf = tid & 1;
    const int arow  = blockM + lrow;
    const bool aok  = arow < M;
    const float* aptr = A  + (size_t)(aok ? arow : 0) * KDIM + lhalf * 16;
    const float* bptr = Bm + (size_t)(blockN + lrow) * KDIM + lhalf * 16;
    const uint32_t adst = sbase + (uint32_t)(lrow * ASTRIDE + lhalf * 16) * 4;
    const uint32_t bdst = adst + ABLK_F * 4;
    const int asz = aok ? 16 : 0;

#define LOADC(c) do {                                                          \
        uint32_t _so = ((c) % 3) * (STAGE_F * 4);                              \
        const float* _as = aptr + (c) * 32;                                    \
        const float* _bs = bptr + (c) * 32;                                    \
        _Pragma("unroll")                                                      \
        for (int _i = 0; _i < 4; ++_i)                                         \
            asm volatile("cp.async.cg.shared.global [%0], [%1], 16, %2;"       \
                :: "r"(adst + _so + _i * 16), "l"(_as + _i * 4), "r"(asz));    \
        _Pragma("unroll")                                                      \
        for (int _i = 0; _i < 4; ++_i)                                         \
            asm volatile("cp.async.cg.shared.global [%0], [%1], 16, 16;"       \
                :: "r"(bdst + _so + _i * 16), "l"(_bs + _i * 4));              \
        asm volatile("cp.async.commit_group;");                                \
    } while (0)

    const int lane  = tid & 31;
    const int wid   = tid >> 5;
    const int warpM = (wid & 3) * 32;
    const int warpN = (wid >> 2) * 64;
    const int tq    = lane >> 2;
    const int tr    = lane & 3;

    // ldmatrix per-lane row bases (byte offsets within a stage)
    const int lj = lane >> 3;            // matrix index 0..3
    const int lr = lane & 7;             // row within matrix
    // A matrices: [m-lo left][m-hi left][m-lo right][m-hi right]
    const uint32_t aoff =
        (uint32_t)((warpM + ((lj & 1) << 3) + lr) * ASTRIDE + ((lj >> 1) << 2)) * 4;
    // B matrices: [nt0 left][nt0 right][nt1 left][nt1 right]
    const uint32_t boff = (uint32_t)ABLK_F * 4 +
        (uint32_t)((warpN + ((lj >> 1) << 3) + lr) * ASTRIDE + ((lj & 1) << 2)) * 4;

    float acc[2][8][4];
#pragma unroll
    for (int mt = 0; mt < 2; ++mt)
#pragma unroll
        for (int nt = 0; nt < 8; ++nt)
#pragma unroll
            for (int e = 0; e < 4; ++e) acc[mt][nt][e] = 0.f;

    LOADC(0);
    LOADC(1);

    for (int c = 0; c < NCHUNK; ++c) {
        if (c + 1 < NCHUNK) asm volatile("cp.async.wait_group 1;");
        else                asm volatile("cp.async.wait_group 0;");
        __syncthreads();   // all warps see chunk c; all done computing c-1
        if (c + 2 < NCHUNK) LOADC(c + 2);

        const uint32_t stg = sbase + (uint32_t)((c % 3) * STAGE_F * 4);

#pragma unroll
        for (int ks = 0; ks < 4; ++ks) {
            uint32_t af[2][4];
#pragma unroll
            for (int mt = 0; mt < 2; ++mt)
                ldsm4(af[mt], stg + aoff +
                      (uint32_t)((mt * 16 * ASTRIDE + ks * 8) * 4));
            uint32_t bf[4][4];
#pragma unroll
            for (int p = 0; p < 4; ++p)
                ldsm4(bf[p], stg + boff +
                      (uint32_t)((p * 16 * ASTRIDE + ks * 8) * 4));
#pragma unroll
            for (int p = 0; p < 4; ++p)
#pragma unroll
                for (int mt = 0; mt < 2; ++mt) {
                    mma_tf32(acc[mt][2 * p],     af[mt], &bf[p][0]);
                    mma_tf32(acc[mt][2 * p + 1], af[mt], &bf[p][2]);
                }
        }
    }
#undef LOADC

#pragma unroll
    for (int mt = 0; mt < 2; ++mt) {
#pragma unroll
        for (int half = 0; half < 2; ++half) {
            const int row = blockM + warpM + mt * 16 + tq + half * 8;
            if (row >= M) continue;
            int b = 0, n = 0;
            if (MODE == 0) { b = row / NN; n = row - b * NN; }
#pragma unroll
            for (int nt = 0; nt < 8; ++nt) {
                const int col = blockN + warpN + nt * 8 + tr * 2;
                const float vx = acc[mt][nt][half * 2 + 0];
                const float vy = acc[mt][nt][half * 2 + 1];
                if (MODE == 0) {
                    const int s   = col / CC;
                    const int rem = col - s * CC;
                    const int h   = rem >> 6;
                    const int d   = rem & 63;
                    const float scl = (s == 0) ? (0.125f * LOG2E) : 1.f;
                    float* dp = (s == 0 ? g_q : (s == 1 ? g_k : g_v)) +
                                (((size_t)b * HH + h) * NN + n) * HD + d;
                    *reinterpret_cast<float2*>(dp) = make_float2(vx * scl, vy * scl);
                } else {
                    *reinterpret_cast<float2*>(Cout + (size_t)row * CC + col) =
                        make_float2(vx + bias[col], vy + bias[col + 1]);
                }
            }
        }
    }
}

// ---------------------------------------------------------------------------
// Bias precompute, pre-scaled by log2e (rows 0..784; pad rows stay zero)
// ---------------------------------------------------------------------------
__global__ void __launch_bounds__(256)
bias_kernel(const float* __restrict__ rel_table,
            const float* __restrict__ g2l,
            const float* __restrict__ g2g)
{
    const int h = blockIdx.x;
    const int i = blockIdx.y;
    float* row = g_bias + ((size_t)h * BROWS + i) * BSTR;
    const int xi = (i - 1) / WXY, yi = (i - 1) % WXY;
    for (int j = threadIdx.x; j < NN; j += 256) {
        float v;
        if (i == 0)      v = (j == 0) ? g2g[h] : g2l[h];
        else if (j == 0) v = g2l[HH + h];
        else {
            int xj = (j - 1) / WXY, yj = (j - 1) % WXY;
            int idx = (xi - xj + (WXY - 1)) * RELW + (yi - yj + (WXY - 1));
            v = rel_table[idx * HH + h];
        }
        row[j] = v * LOG2E;
    }
}

// ---------------------------------------------------------------------------
// Flash attention on mma.sync tf32.  KT=32, 3-stage cp.async, one sync/tile,
// base-2 softmax; K and P fragments via ldmatrix.b16.
// ---------------------------------------------------------------------------
#define KT     32
#define NKT    25                         // ceil(785/32)
#define QP_F   (128 * 68)                 // 8704
#define KS_F   (KT * 68)                  // 2176
#define VS_F   (KT * 72)                  // 2304
#define ATTN_SMEM ((QP_F + 3 * (KS_F + VS_F)) * 4)   // 88576 B -> 2 CTA/SM

__global__ void __launch_bounds__(256, 2)
attn_mma()
{
    extern __shared__ float sm[];
    float* QP = sm;                       // Q staging, then P (per-warp rows)
    const uint32_t sbase = smem_u32(sm);

    const int bh = blockIdx.y;
    const int b  = bh / HH;
    const int h  = bh - b * HH;
    const int q0 = blockIdx.x * 128;

    const int tid  = threadIdx.x;
    const int lane = tid & 31;
    const int wid  = tid >> 5;
    const int tq   = lane >> 2;
    const int tr   = lane & 3;
    const int r0   = wid * 16;

    const float* Qg = g_q + (size_t)bh * NN * HD;
    const float* Kg = g_k + (size_t)bh * NN * HD;
    const float* Vg = g_v + (size_t)bh * NN * HD;
    const float* Bh = g_bias + (size_t)h * BROWS * BSTR;

    // ldmatrix per-lane row bases
    const int lj = lane >> 3;
    const int lr = lane & 7;
    // K (B-type): [nt0 left][nt0 right][nt1 left][nt1 right], stride 68
    const uint32_t koff =
        (uint32_t)(((((lj >> 1) << 3) + lr) * 68) + ((lj & 1) << 2)) * 4;
    // P (A-type): [r-lo left][r-hi left][r-lo right][r-hi right], stride 68
    const uint32_t poff =
        (uint32_t)(((r0 + ((lj & 1) << 3) + lr) * 68) + ((lj >> 1) << 2)) * 4;

    // ---- stage Q tile [128][64] into QP (stride 68) ----
#pragma unroll
    for (int u = 0; u < 8; ++u) {
        const int lin = tid + u * 256;
        const int row = lin >> 4;
        const int c4  = (lin & 15) * 4;
        const int gi  = q0 + row;
        float4 v = make_float4(0.f, 0.f, 0.f, 0.f);
        if (gi < NN) v = *reinterpret_cast<const float4*>(Qg + (size_t)gi * HD + c4);
        *reinterpret_cast<float4*>(QP + row * 68 + c4) = v;
    }
    __syncthreads();

    // ---- Q A-fragments to registers (loop-invariant; via ldmatrix) ----
    uint32_t qf[8][4];
#pragma unroll
    for (int ks = 0; ks < 8; ++ks)
        ldsm4(qf[ks], sbase + poff + (uint32_t)(ks * 8 * 4));
    __syncthreads();    // QP now free -> P buffer

    // ---- K/V cp.async mapping: 32 rows x 64B; 2 x 16B per thread each ----
    const int lrow = tid >> 4;            // 0..15
    const int lc4  = (tid & 15) * 4;

#define KV_LOAD(kt) do {                                                        \
        const int _k0 = (kt) * KT;                                              \
        const uint32_t _ks = sbase + (QP_F + ((kt) % 3) * (KS_F + VS_F)) * 4;   \
        const uint32_t _vs = _ks + KS_F * 4;                                    \
        _Pragma("unroll")                                                       \
        for (int _u = 0; _u < 2; ++_u) {                                        \
            const int _r = lrow + _u * 16;                                      \
            const int _j = _k0 + _r;                                            \
            const int _sz = (_j < NN) ? 16 : 0;                                 \
            asm volatile("cp.async.cg.shared.global [%0], [%1], 16, %2;"        \
                :: "r"(_ks + (_r * 68 + lc4) * 4),                              \
                   "l"(Kg + (size_t)_j * HD + lc4), "r"(_sz));                  \
            asm volatile("cp.async.cg.shared.global [%0], [%1], 16, %2;"        \
                :: "r"(_vs + (_r * 72 + lc4) * 4),                              \
                   "l"(Vg + (size_t)_j * HD + lc4), "r"(_sz));                  \
        }                                                                       \
        asm volatile("cp.async.commit_group;");                                 \
    } while (0)

    float oacc[8][4];
#pragma unroll
    for (int nt = 0; nt < 8; ++nt)
#pragma unroll
        for (int e = 0; e < 4; ++e) oacc[nt][e] = 0.f;
    float mrow[2] = {-1e30f, -1e30f};
    float lrow_s[2] = {0.f, 0.f};

    KV_LOAD(0);
    KV_LOAD(1);

    for (int kt = 0; kt < NKT; ++kt) {
        const int k0 = kt * KT;
        if (kt + 1 < NKT) asm volatile("cp.async.wait_group 1;");
        else              asm volatile("cp.async.wait_group 0;");
        __syncthreads();   // tile kt visible; all warps done with tile kt-1
        if (kt + 2 < NKT) KV_LOAD(kt + 2);

        const uint32_t ksAddr = sbase + (QP_F + (kt % 3) * (KS_F + VS_F)) * 4;
        const float*   Vs     = sm + QP_F + (kt % 3) * (KS_F + VS_F) + KS_F;

        // ---- S = Q K^T  (128 x 32), K fragments via ldmatrix ----
        float sacc[4][4];
#pragma unroll
        for (int nt = 0; nt < 4; ++nt)
#pragma unroll
            for (int e = 0; e < 4; ++e) sacc[nt][e] = 0.f;

#pragma unroll
        for (int ks = 0; ks < 8; ++ks) {
            uint32_t bk[2][4];
#pragma unroll
            for (int p = 0; p < 2; ++p)
                ldsm4(bk[p], ksAddr + koff +
                      (uint32_t)((p * 16 * 68 + ks * 8) * 4));
#pragma unroll
            for (int p = 0; p < 2; ++p) {
                mma_tf32(sacc[2 * p],     qf[ks], &bk[p][0]);
                mma_tf32(sacc[2 * p + 1], qf[ks], &bk[p][2]);
            }
        }

        // ---- bias add (already log2e-scaled) ----
#pragma unroll
        for (int nt = 0; nt < 4; ++nt) {
#pragma unroll
            for (int hh = 0; hh < 2; ++hh) {
                const int row = q0 + r0 + tq + 8 * hh;
                const int col = k0 + nt * 8 + 2 * tr;
                const float2 bb = __ldg(reinterpret_cast<const float2*>(
                    Bh + (size_t)row * BSTR + col));
                sacc[nt][2 * hh + 0] += bb.x;
                sacc[nt][2 * hh + 1] += bb.y;
            }
        }
        // ---- mask invalid keys (last tile only) ----
        if (k0 + KT > NN) {
#pragma unroll
            for (int nt = 0; nt < 4; ++nt)
#pragma unroll
                for (int e = 0; e < 4; ++e) {
                    const int col = k0 + nt * 8 + 2 * tr + (e & 1);
                    if (col >= NN) sacc[nt][e] = -1e30f;
                }
        }

        // ---- online softmax, base 2 (rows tq, tq+8; quad-local) ----
#pragma unroll
        for (int hh = 0; hh < 2; ++hh) {
            float mx = -1e30f;
#pragma unroll
            for (int nt = 0; nt < 4; ++nt)
                mx = fmaxf(mx, fmaxf(sacc[nt][2 * hh], sacc[nt][2 * hh + 1]));
            mx = fmaxf(mx, __shfl_xor_sync(0xffffffffu, mx, 1));
            mx = fmaxf(mx, __shfl_xor_sync(0xffffffffu, mx, 2));
            const float mnew = fmaxf(mrow[hh], mx);
            const float corr = ex2(mrow[hh] - mnew);
            mrow[hh] = mnew;
            float ps = 0.f;
#pragma unroll
            for (int nt = 0; nt < 4; ++nt) {
                const float e0 = ex2(sacc[nt][2 * hh] - mnew);
                const float e1 = ex2(sacc[nt][2 * hh + 1] - mnew);
                sacc[nt][2 * hh] = e0; sacc[nt][2 * hh + 1] = e1;
                ps += e0 + e1;
            }
            ps += __shfl_xor_sync(0xffffffffu, ps, 1);
            ps += __shfl_xor_sync(0xffffffffu, ps, 2);
            lrow_s[hh] = lrow_s[hh] * corr + ps;
#pragma unroll
            for (int nt = 0; nt < 8; ++nt) {
                oacc[nt][2 * hh] *= corr;
                oacc[nt][2 * hh + 1] *= corr;
            }
        }

        // ---- stage P to smem (per-warp rows; warp-local hazard only) ----
#pragma unroll
        for (int nt = 0; nt < 4; ++nt) {
            *reinterpret_cast<float2*>(QP + (r0 + tq) * 68 + nt * 8 + 2 * tr) =
                make_float2(sacc[nt][0], sacc[nt][1]);
            *reinterpret_cast<float2*>(QP + (r0 + tq + 8) * 68 + nt * 8 + 2 * tr) =
                make_float2(sacc[nt][2], sacc[nt][3]);
        }
        __syncwarp();

        // ---- O += P V  (k-dim = 32), P fragments via ldmatrix ----
#pragma unroll
        for (int ks = 0; ks < 4; ++ks) {
            uint32_t af[4];
            ldsm4(af, sbase + poff + (uint32_t)(ks * 8 * 4));
#pragma unroll
            for (int nt = 0; nt < 8; ++nt) {
                const float* bp = Vs + (ks * 8 + tr) * 72 + nt * 8 + tq;
                uint32_t bf[2] = { __float_as_uint(bp[0]),
                                   __float_as_uint(bp[4 * 72]) };
                mma_tf32(oacc[nt], af, bf);
            }
        }
        // no end-of-loop sync: next iteration's single sync covers reuse
    }
#undef KV_LOAD

    // ---- normalize + write g_ao (tf32-rounded) ----
#pragma unroll
    for (int hh = 0; hh < 2; ++hh) {
        const int i = q0 + r0 + tq + 8 * hh;
        if (i < NN) {
            const float inv = 1.f / lrow_s[hh];
#pragma unroll
            for (int nt = 0; nt < 8; ++nt) {
                float2 w = make_float2(oacc[nt][2 * hh] * inv,
                                       oacc[nt][2 * hh + 1] * inv);
                w.x = rna_tf32(w.x); w.y = rna_tf32(w.y);
                *reinterpret_cast<float2*>(
                    g_ao + ((size_t)b * NN + i) * CC + h * HD + nt * 8 + 2 * tr) = w;
            }
        }
    }
}

// ---------------------------------------------------------------------------
extern "C" void kernel_launch(void* const* d_in, const int* in_sizes, int n_in,
                              void* d_out, int out_size)
{
    const float* x         = (const float*)d_in[0];
    const float* qkv_w     = (const float*)d_in[1];
    const float* proj_w    = (const float*)d_in[2];
    const float* proj_b    = (const float*)d_in[3];
    const float* rel_table = (const float*)d_in[4];
    const float* g2l       = (const float*)d_in[5];
    const float* g2g       = (const float*)d_in[6];
    float* out = (float*)d_out;

    (void)in_sizes; (void)n_in; (void)out_size;

    cudaFuncSetAttribute(attn_mma,
                         cudaFuncAttributeMaxDynamicSharedMemorySize, ATTN_SMEM);
    cudaFuncSetAttribute(gemm_mma<0>,
                         cudaFuncAttributeMaxDynamicSharedMemorySize, GEMM_SMEM);
    cudaFuncSetAttribute(gemm_mma<1>,
                         cudaFuncAttributeMaxDynamicSharedMemorySize, GEMM_SMEM);

    // 0) tf32 rounding (single launch) + bias precompute
    {
        int n4 = N4X + N4Q + N4P;
        round_all<<<(n4 + 255) / 256, 256>>>(x, qkv_w, proj_w);
        dim3 gb(HH, NN);
        bias_kernel<<<gb, 256>>>(rel_table, g2l, g2g);
    }
    // 1) QKV GEMM (tf32 mma.sync + ldmatrix)
    {
        dim3 grid(QKVN / 128, (MROWS + 127) / 128);   // (18, 99)
        gemm_mma<0><<<grid, 256, GEMM_SMEM>>>(nullptr, nullptr, MROWS);
    }
    // 2) flash attention (tf32 mma.sync + ldmatrix) -> g_ao
    {
        dim3 grid((NN + 127) / 128, BB * HH);         // (7, 192)
        attn_mma<<<grid, 256, ATTN_SMEM>>>();
    }
    // 3) proj GEMM (tf32 mma.sync + ldmatrix) + bias -> out
    {
        dim3 grid(CC / 128, (MROWS + 127) / 128);     // (6, 99)
        gemm_mma<1><<<grid, 256, GEMM_SMEM>>>(proj_b, out, MROWS);
    }
}

// round 17
// speedup vs baseline: 1.0218x; 1.0083x over previous
#include <cuda_runtime.h>
#include <cuda_bf16.h>
#include <cstdint>

// Problem constants
#define BB    16
#define NN    785
#define CC    768
#define HH    12
#define HD    64
#define MROWS (BB * NN)      // 12560
#define QKVN  (3 * CC)       // 2304
#define WXY   28
#define RELW  55
#define BROWS 896            // padded query rows for bias (7 * 128)
#define BSTR  836
#define KDIM  768
#define NCHUNK 24            // 768 / 32
#define LOG2E 1.4426950408889634f

// -------- scratch (static device arrays; no allocations allowed) ----------
__device__ float g_x32[MROWS * CC];          // x rounded to tf32
__device__ float g_wq [QKVN * CC];           // qkv_w rounded to tf32
__device__ float g_wp [CC * CC];             // proj_w rounded to tf32
__device__ float g_q  [BB * HH * NN * HD];   // [B,H,N,64], Q scaled 1/8*log2e
__device__ float g_k  [BB * HH * NN * HD];
__device__ float g_v  [BB * HH * NN * HD];
__device__ float g_ao [MROWS * CC];          // attention out (tf32-rounded)
__device__ float g_bias[HH * BROWS * BSTR];  // [h][i][j] bias*log2e (pads 0)

// ---------------------------------------------------------------------------
__device__ __forceinline__ uint32_t smem_u32(const void* p) {
    uint32_t a;
    asm("{ .reg .u64 t; cvta.to.shared.u64 t, %1; cvt.u32.u64 %0, t; }"
        : "=r"(a) : "l"(p));
    return a;
}
__device__ __forceinline__ float rna_tf32(float v) {
    uint32_t u;
    asm("cvt.rna.tf32.f32 %0, %1;" : "=r"(u) : "f"(v));
    return __uint_as_float(u);
}
__device__ __forceinline__ float ex2(float x) {
    float r;
    asm("ex2.approx.f32 %0, %1;" : "=f"(r) : "f"(x));
    return r;
}
__device__ __forceinline__ void mma_tf32(float* d, const uint32_t* a,
                                         const uint32_t* b) {
    asm volatile(
        "mma.sync.aligned.m16n8k8.row.col.f32.tf32.tf32.f32 "
        "{%0,%1,%2,%3}, {%4,%5,%6,%7}, {%8,%9}, {%0,%1,%2,%3};"
        : "+f"(d[0]), "+f"(d[1]), "+f"(d[2]), "+f"(d[3])
        : "r"(a[0]), "r"(a[1]), "r"(a[2]), "r"(a[3]), "r"(b[0]), "r"(b[1]));
}
// ldmatrix x4: one call = one tf32 A-fragment (m16k8) or two B-fragments (n8k8)
__device__ __forceinline__ void ldsm4(uint32_t* r, uint32_t addr) {
    asm volatile(
        "ldmatrix.sync.aligned.m8n8.x4.shared.b16 {%0,%1,%2,%3}, [%4];"
        : "=r"(r[0]), "=r"(r[1]), "=r"(r[2]), "=r"(r[3]) : "r"(addr));
}

// ---------------------------------------------------------------------------
// Combined prep: tf32 rounding of x/qkv_w/proj_w AND bias precompute
// in ONE launch (bias blocks overlap the rounding blocks' streaming).
// ---------------------------------------------------------------------------
#define N4X (MROWS * CC / 4)
#define N4Q (QKVN * CC / 4)
#define N4P (CC * CC / 4)
#define RND_BLKS ((N4X + N4Q + N4P + 255) / 256)
#define BIAS_BLKS (HH * NN)

__global__ void __launch_bounds__(256)
prep_all(const float* __restrict__ x, const float* __restrict__ wq,
         const float* __restrict__ wp, const float* __restrict__ rel_table,
         const float* __restrict__ g2l, const float* __restrict__ g2g)
{
    const int blk = blockIdx.x;
    if (blk < RND_BLKS) {
        int i = blk * 256 + threadIdx.x;
        const float* src;
        float* dst;
        if (i < N4X)                  { src = x;  dst = g_x32; }
        else if (i < N4X + N4Q)       { src = wq; dst = g_wq;  i -= N4X; }
        else if (i < N4X + N4Q + N4P) { src = wp; dst = g_wp;  i -= N4X + N4Q; }
        else return;
        float4 v = reinterpret_cast<const float4*>(src)[i];
        v.x = rna_tf32(v.x); v.y = rna_tf32(v.y);
        v.z = rna_tf32(v.z); v.w = rna_tf32(v.w);
        reinterpret_cast<float4*>(dst)[i] = v;
    } else {
        const int bb = blk - RND_BLKS;        // 0 .. HH*NN-1
        const int h  = bb / NN;
        const int i  = bb - h * NN;
        float* row = g_bias + ((size_t)h * BROWS + i) * BSTR;
        const int xi = (i - 1) / WXY, yi = (i - 1) % WXY;
        for (int j = threadIdx.x; j < NN; j += 256) {
            float v;
            if (i == 0)      v = (j == 0) ? g2g[h] : g2l[h];
            else if (j == 0) v = g2l[HH + h];
            else {
                int xj = (j - 1) / WXY, yj = (j - 1) % WXY;
                int idx = (xi - xj + (WXY - 1)) * RELW + (yi - yj + (WXY - 1));
                v = rel_table[idx * HH + h];
            }
            row[j] = v * LOG2E;
        }
    }
}

// ---------------------------------------------------------------------------
// tf32 mma.sync NT GEMM — 3-stage cp.async, one sync per chunk,
// fragments via ldmatrix.b16 (A: 2 ldsm/ks, B: 4 ldsm/ks).
// ---------------------------------------------------------------------------
#define ASTRIDE   36
#define ABLK_F    (128 * ASTRIDE)
#define STAGE_F   (2 * ABLK_F)
#define GEMM_SMEM (3 * STAGE_F * 4)      // 110592 B -> 2 CTAs/SM

template <int MODE>
__global__ void __launch_bounds__(256, 2)
gemm_mma(const float* __restrict__ bias, float* __restrict__ Cout, int M)
{
    extern __shared__ float sm[];
    const uint32_t sbase = smem_u32(sm);

    const float* __restrict__ A  = (MODE == 0) ? g_x32 : g_ao;
    const float* __restrict__ Bm = (MODE == 0) ? g_wq  : g_wp;

    const int tid    = threadIdx.x;
    const int blockM = blockIdx.y * 128;
    const int blockN = blockIdx.x * 128;

    const int lrow  = tid >> 1;
    const int lhalf = tid & 1;
    const int arow  = blockM + lrow;
    const bool aok  = arow < M;
    const float* aptr = A  + (size_t)(aok ? arow : 0) * KDIM + lhalf * 16;
    const float* bptr = Bm + (size_t)(blockN + lrow) * KDIM + lhalf * 16;
    const uint32_t adst = sbase + (uint32_t)(lrow * ASTRIDE + lhalf * 16) * 4;
    const uint32_t bdst = adst + ABLK_F * 4;
    const int asz = aok ? 16 : 0;

#define LOADC(c) do {                                                          \
        uint32_t _so = ((c) % 3) * (STAGE_F * 4);                              \
        const float* _as = aptr + (c) * 32;                                    \
        const float* _bs = bptr + (c) * 32;                                    \
        _Pragma("unroll")                                                      \
        for (int _i = 0; _i < 4; ++_i)                                         \
            asm volatile("cp.async.cg.shared.global [%0], [%1], 16, %2;"       \
                :: "r"(adst + _so + _i * 16), "l"(_as + _i * 4), "r"(asz));    \
        _Pragma("unroll")                                                      \
        for (int _i = 0; _i < 4; ++_i)                                         \
            asm volatile("cp.async.cg.shared.global [%0], [%1], 16, 16;"       \
                :: "r"(bdst + _so + _i * 16), "l"(_bs + _i * 4));              \
        asm volatile("cp.async.commit_group;");                                \
    } while (0)

    const int lane  = tid & 31;
    const int wid   = tid >> 5;
    const int warpM = (wid & 3) * 32;
    const int warpN = (wid >> 2) * 64;
    const int tq    = lane >> 2;
    const int tr    = lane & 3;

    // ldmatrix per-lane row bases (byte offsets within a stage)
    const int lj = lane >> 3;            // matrix index 0..3
    const int lr = lane & 7;             // row within matrix
    // A matrices: [m-lo left][m-hi left][m-lo right][m-hi right]
    const uint32_t aoff =
        (uint32_t)((warpM + ((lj & 1) << 3) + lr) * ASTRIDE + ((lj >> 1) << 2)) * 4;
    // B matrices: [nt0 left][nt0 right][nt1 left][nt1 right]
    const uint32_t boff = (uint32_t)ABLK_F * 4 +
        (uint32_t)((warpN + ((lj >> 1) << 3) + lr) * ASTRIDE + ((lj & 1) << 2)) * 4;

    float acc[2][8][4];
#pragma unroll
    for (int mt = 0; mt < 2; ++mt)
#pragma unroll
        for (int nt = 0; nt < 8; ++nt)
#pragma unroll
            for (int e = 0; e < 4; ++e) acc[mt][nt][e] = 0.f;

    LOADC(0);
    LOADC(1);

    for (int c = 0; c < NCHUNK; ++c) {
        if (c + 1 < NCHUNK) asm volatile("cp.async.wait_group 1;");
        else                asm volatile("cp.async.wait_group 0;");
        __syncthreads();   // all warps see chunk c; all done computing c-1
        if (c + 2 < NCHUNK) LOADC(c + 2);

        const uint32_t stg = sbase + (uint32_t)((c % 3) * STAGE_F * 4);

#pragma unroll
        for (int ks = 0; ks < 4; ++ks) {
            uint32_t af[2][4];
#pragma unroll
            for (int mt = 0; mt < 2; ++mt)
                ldsm4(af[mt], stg + aoff +
                      (uint32_t)((mt * 16 * ASTRIDE + ks * 8) * 4));
            uint32_t bf[4][4];
#pragma unroll
            for (int p = 0; p < 4; ++p)
                ldsm4(bf[p], stg + boff +
                      (uint32_t)((p * 16 * ASTRIDE + ks * 8) * 4));
#pragma unroll
            for (int p = 0; p < 4; ++p)
#pragma unroll
                for (int mt = 0; mt < 2; ++mt) {
                    mma_tf32(acc[mt][2 * p],     af[mt], &bf[p][0]);
                    mma_tf32(acc[mt][2 * p + 1], af[mt], &bf[p][2]);
                }
        }
    }
#undef LOADC

#pragma unroll
    for (int mt = 0; mt < 2; ++mt) {
#pragma unroll
        for (int half = 0; half < 2; ++half) {
            const int row = blockM + warpM + mt * 16 + tq + half * 8;
            if (row >= M) continue;
            int b = 0, n = 0;
            if (MODE == 0) { b = row / NN; n = row - b * NN; }
#pragma unroll
            for (int nt = 0; nt < 8; ++nt) {
                const int col = blockN + warpN + nt * 8 + tr * 2;
                const float vx = acc[mt][nt][half * 2 + 0];
                const float vy = acc[mt][nt][half * 2 + 1];
                if (MODE == 0) {
                    const int s   = col / CC;
                    const int rem = col - s * CC;
                    const int h   = rem >> 6;
                    const int d   = rem & 63;
                    const float scl = (s == 0) ? (0.125f * LOG2E) : 1.f;
                    float* dp = (s == 0 ? g_q : (s == 1 ? g_k : g_v)) +
                                (((size_t)b * HH + h) * NN + n) * HD + d;
                    *reinterpret_cast<float2*>(dp) = make_float2(vx * scl, vy * scl);
                } else {
                    *reinterpret_cast<float2*>(Cout + (size_t)row * CC + col) =
                        make_float2(vx + bias[col], vy + bias[col + 1]);
                }
            }
        }
    }
}

// ---------------------------------------------------------------------------
// Flash attention on mma.sync tf32.  KT=32, 3-stage cp.async, one sync/tile,
// base-2 softmax; K and P fragments via ldmatrix.b16.
// ---------------------------------------------------------------------------
#define KT     32
#define NKT    25                         // ceil(785/32)
#define QP_F   (128 * 68)                 // 8704
#define KS_F   (KT * 68)                  // 2176
#define VS_F   (KT * 72)                  // 2304
#define ATTN_SMEM ((QP_F + 3 * (KS_F + VS_F)) * 4)   // 88576 B -> 2 CTA/SM

__global__ void __launch_bounds__(256, 2)
attn_mma()
{
    extern __shared__ float sm[];
    float* QP = sm;                       // Q staging, then P (per-warp rows)
    const uint32_t sbase = smem_u32(sm);

    const int bh = blockIdx.y;
    const int b  = bh / HH;
    const int h  = bh - b * HH;
    const int q0 = blockIdx.x * 128;

    const int tid  = threadIdx.x;
    const int lane = tid & 31;
    const int wid  = tid >> 5;
    const int tq   = lane >> 2;
    const int tr   = lane & 3;
    const int r0   = wid * 16;

    const float* Qg = g_q + (size_t)bh * NN * HD;
    const float* Kg = g_k + (size_t)bh * NN * HD;
    const float* Vg = g_v + (size_t)bh * NN * HD;
    const float* Bh = g_bias + (size_t)h * BROWS * BSTR;

    // ldmatrix per-lane row bases
    const int lj = lane >> 3;
    const int lr = lane & 7;
    // K (B-type): [nt0 left][nt0 right][nt1 left][nt1 right], stride 68
    const uint32_t koff =
        (uint32_t)(((((lj >> 1) << 3) + lr) * 68) + ((lj & 1) << 2)) * 4;
    // P (A-type): [r-lo left][r-hi left][r-lo right][r-hi right], stride 68
    const uint32_t poff =
        (uint32_t)(((r0 + ((lj & 1) << 3) + lr) * 68) + ((lj >> 1) << 2)) * 4;

    // ---- stage Q tile [128][64] into QP (stride 68) ----
#pragma unroll
    for (int u = 0; u < 8; ++u) {
        const int lin = tid + u * 256;
        const int row = lin >> 4;
        const int c4  = (lin & 15) * 4;
        const int gi  = q0 + row;
        float4 v = make_float4(0.f, 0.f, 0.f, 0.f);
        if (gi < NN) v = *reinterpret_cast<const float4*>(Qg + (size_t)gi * HD + c4);
        *reinterpret_cast<float4*>(QP + row * 68 + c4) = v;
    }
    __syncthreads();

    // ---- Q A-fragments to registers (loop-invariant; via ldmatrix) ----
    uint32_t qf[8][4];
#pragma unroll
    for (int ks = 0; ks < 8; ++ks)
        ldsm4(qf[ks], sbase + poff + (uint32_t)(ks * 8 * 4));
    __syncthreads();    // QP now free -> P buffer

    // ---- K/V cp.async mapping: 32 rows x 64B; 2 x 16B per thread each ----
    const int lrow = tid >> 4;            // 0..15
    const int lc4  = (tid & 15) * 4;

#define KV_LOAD(kt) do {                                                        \
        const int _k0 = (kt) * KT;                                              \
        const uint32_t _ks = sbase + (QP_F + ((kt) % 3) * (KS_F + VS_F)) * 4;   \
        const uint32_t _vs = _ks + KS_F * 4;                                    \
        _Pragma("unroll")                                                       \
        for (int _u = 0; _u < 2; ++_u) {                                        \
            const int _r = lrow + _u * 16;                                      \
            const int _j = _k0 + _r;                                            \
            const int _sz = (_j < NN) ? 16 : 0;                                 \
            asm volatile("cp.async.cg.shared.global [%0], [%1], 16, %2;"        \
                :: "r"(_ks + (_r * 68 + lc4) * 4),                              \
                   "l"(Kg + (size_t)_j * HD + lc4), "r"(_sz));                  \
            asm volatile("cp.async.cg.shared.global [%0], [%1], 16, %2;"        \
                :: "r"(_vs + (_r * 72 + lc4) * 4),                              \
                   "l"(Vg + (size_t)_j * HD + lc4), "r"(_sz));                  \
        }                                                                       \
        asm volatile("cp.async.commit_group;");                                 \
    } while (0)

    float oacc[8][4];
#pragma unroll
    for (int nt = 0; nt < 8; ++nt)
#pragma unroll
        for (int e = 0; e < 4; ++e) oacc[nt][e] = 0.f;
    float mrow[2] = {-1e30f, -1e30f};
    float lrow_s[2] = {0.f, 0.f};

    KV_LOAD(0);
    KV_LOAD(1);

    for (int kt = 0; kt < NKT; ++kt) {
        const int k0 = kt * KT;
        if (kt + 1 < NKT) asm volatile("cp.async.wait_group 1;");
        else              asm volatile("cp.async.wait_group 0;");
        __syncthreads();   // tile kt visible; all warps done with tile kt-1
        if (kt + 2 < NKT) KV_LOAD(kt + 2);

        const uint32_t ksAddr = sbase + (QP_F + (kt % 3) * (KS_F + VS_F)) * 4;
        const float*   Vs     = sm + QP_F + (kt % 3) * (KS_F + VS_F) + KS_F;

        // ---- S = Q K^T  (128 x 32), K fragments via ldmatrix ----
        float sacc[4][4];
#pragma unroll
        for (int nt = 0; nt < 4; ++nt)
#pragma unroll
            for (int e = 0; e < 4; ++e) sacc[nt][e] = 0.f;

#pragma unroll
        for (int ks = 0; ks < 8; ++ks) {
            uint32_t bk[2][4];
#pragma unroll
            for (int p = 0; p < 2; ++p)
                ldsm4(bk[p], ksAddr + koff +
                      (uint32_t)((p * 16 * 68 + ks * 8) * 4));
#pragma unroll
            for (int p = 0; p < 2; ++p) {
                mma_tf32(sacc[2 * p],     qf[ks], &bk[p][0]);
                mma_tf32(sacc[2 * p + 1], qf[ks], &bk[p][2]);
            }
        }

        // ---- bias add (already log2e-scaled) ----
#pragma unroll
        for (int nt = 0; nt < 4; ++nt) {
#pragma unroll
            for (int hh = 0; hh < 2; ++hh) {
                const int row = q0 + r0 + tq + 8 * hh;
                const int col = k0 + nt * 8 + 2 * tr;
                const float2 bb = __ldg(reinterpret_cast<const float2*>(
                    Bh + (size_t)row * BSTR + col));
                sacc[nt][2 * hh + 0] += bb.x;
                sacc[nt][2 * hh + 1] += bb.y;
            }
        }
        // ---- mask invalid keys (last tile only) ----
        if (k0 + KT > NN) {
#pragma unroll
            for (int nt = 0; nt < 4; ++nt)
#pragma unroll
                for (int e = 0; e < 4; ++e) {
                    const int col = k0 + nt * 8 + 2 * tr + (e & 1);
                    if (col >= NN) sacc[nt][e] = -1e30f;
                }
        }

        // ---- online softmax, base 2 (rows tq, tq+8; quad-local) ----
#pragma unroll
        for (int hh = 0; hh < 2; ++hh) {
            float mx = -1e30f;
#pragma unroll
            for (int nt = 0; nt < 4; ++nt)
                mx = fmaxf(mx, fmaxf(sacc[nt][2 * hh], sacc[nt][2 * hh + 1]));
            mx = fmaxf(mx, __shfl_xor_sync(0xffffffffu, mx, 1));
            mx = fmaxf(mx, __shfl_xor_sync(0xffffffffu, mx, 2));
            const float mnew = fmaxf(mrow[hh], mx);
            const float corr = ex2(mrow[hh] - mnew);
            mrow[hh] = mnew;
            float ps = 0.f;
#pragma unroll
            for (int nt = 0; nt < 4; ++nt) {
                const float e0 = ex2(sacc[nt][2 * hh] - mnew);
                const float e1 = ex2(sacc[nt][2 * hh + 1] - mnew);
                sacc[nt][2 * hh] = e0; sacc[nt][2 * hh + 1] = e1;
                ps += e0 + e1;
            }
            ps += __shfl_xor_sync(0xffffffffu, ps, 1);
            ps += __shfl_xor_sync(0xffffffffu, ps, 2);
            lrow_s[hh] = lrow_s[hh] * corr + ps;
#pragma unroll
            for (int nt = 0; nt < 8; ++nt) {
                oacc[nt][2 * hh] *= corr;
                oacc[nt][2 * hh + 1] *= corr;
            }
        }

        // ---- stage P to smem (per-warp rows; warp-local hazard only) ----
#pragma unroll
        for (int nt = 0; nt < 4; ++nt) {
            *reinterpret_cast<float2*>(QP + (r0 + tq) * 68 + nt * 8 + 2 * tr) =
                make_float2(sacc[nt][0], sacc[nt][1]);
            *reinterpret_cast<float2*>(QP + (r0 + tq + 8) * 68 + nt * 8 + 2 * tr) =
                make_float2(sacc[nt][2], sacc[nt][3]);
        }
        __syncwarp();

        // ---- O += P V  (k-dim = 32), P fragments via ldmatrix ----
#pragma unroll
        for (int ks = 0; ks < 4; ++ks) {
            uint32_t af[4];
            ldsm4(af, sbase + poff + (uint32_t)(ks * 8 * 4));
#pragma unroll
            for (int nt = 0; nt < 8; ++nt) {
                const float* bp = Vs + (ks * 8 + tr) * 72 + nt * 8 + tq;
                uint32_t bf[2] = { __float_as_uint(bp[0]),
                                   __float_as_uint(bp[4 * 72]) };
                mma_tf32(oacc[nt], af, bf);
            }
        }
        // no end-of-loop sync: next iteration's single sync covers reuse
    }
#undef KV_LOAD

    // ---- normalize + write g_ao (tf32-rounded) ----
#pragma unroll
    for (int hh = 0; hh < 2; ++hh) {
        const int i = q0 + r0 + tq + 8 * hh;
        if (i < NN) {
            const float inv = 1.f / lrow_s[hh];
#pragma unroll
            for (int nt = 0; nt < 8; ++nt) {
                float2 w = make_float2(oacc[nt][2 * hh] * inv,
                                       oacc[nt][2 * hh + 1] * inv);
                w.x = rna_tf32(w.x); w.y = rna_tf32(w.y);
                *reinterpret_cast<float2*>(
                    g_ao + ((size_t)b * NN + i) * CC + h * HD + nt * 8 + 2 * tr) = w;
            }
        }
    }
}

// ---------------------------------------------------------------------------
extern "C" void kernel_launch(void* const* d_in, const int* in_sizes, int n_in,
                              void* d_out, int out_size)
{
    const float* x         = (const float*)d_in[0];
    const float* qkv_w     = (const float*)d_in[1];
    const float* proj_w    = (const float*)d_in[2];
    const float* proj_b    = (const float*)d_in[3];
    const float* rel_table = (const float*)d_in[4];
    const float* g2l       = (const float*)d_in[5];
    const float* g2g       = (const float*)d_in[6];
    float* out = (float*)d_out;

    (void)in_sizes; (void)n_in; (void)out_size;

    cudaFuncSetAttribute(attn_mma,
                         cudaFuncAttributeMaxDynamicSharedMemorySize, ATTN_SMEM);
    cudaFuncSetAttribute(gemm_mma<0>,
                         cudaFuncAttributeMaxDynamicSharedMemorySize, GEMM_SMEM);
    cudaFuncSetAttribute(gemm_mma<1>,
                         cudaFuncAttributeMaxDynamicSharedMemorySize, GEMM_SMEM);

    // 0) combined tf32 rounding + bias precompute (single launch)
    {
        prep_all<<<RND_BLKS + BIAS_BLKS, 256>>>(x, qkv_w, proj_w,
                                                rel_table, g2l, g2g);
    }
    // 1) QKV GEMM (tf32 mma.sync + ldmatrix)
    {
        dim3 grid(QKVN / 128, (MROWS + 127) / 128);   // (18, 99)
        gemm_mma<0><<<grid, 256, GEMM_SMEM>>>(nullptr, nullptr, MROWS);
    }
    // 2) flash attention (tf32 mma.sync + ldmatrix) -> g_ao
    {
        dim3 grid((NN + 127) / 128, BB * HH);         // (7, 192)
        attn_mma<<<grid, 256, ATTN_SMEM>>>();
    }
    // 3) proj GEMM (tf32 mma.sync + ldmatrix) + bias -> out
    {
        dim3 grid(CC / 128, (MROWS + 127) / 128);     // (6, 99)
        gemm_mma<1><<<grid, 256, GEMM_SMEM>>>(proj_b, out, MROWS);
    }
}